// round 17
// baseline (speedup 1.0000x reference)
#include <cuda_runtime.h>
#include <cuda_bf16.h>
#include <math.h>

// Problem constants (fixed by the dataset)
#define N_    8192
#define C_    19
#define M_    10
#define CM_   190         // C_*M_
#define K_    64
#define PVN   (C_*M_*K_)  // 12160
#define TPB   256

// dynamic smem layout (32-bit words)
#define FRAGB_WORDS (24 * 8 * 32 * 2)   // 24 tiles x 8 ks x 32 lanes x uint2
#define OFF_FRAGA   (FRAGB_WORDS)                 // 1024 words (8*32*4)
#define OFF_BASE    (OFF_FRAGA + 8 * 32 * 4)      // 16 words
#define OFF_OUT     (OFF_BASE + 16)               // 3040 words
#define SMEM_WORDS  (OFF_OUT + 16 * CM_)
#define SMEM_BYTES  (SMEM_WORDS * 4)              // 65472

// word offset between the p^2 region (ks 0..3) and p region (ks 4..7) of a tile
#define P_KS_OFFSET (4 * 32 * 2)   // 4 ksteps x 32 lanes x 2 words = 256

// ---- mma.sync m16n8k16 bf16 -> f32 ------------------------------------------
__device__ __forceinline__ void mma16816(float* d,
                                         unsigned a0, unsigned a1,
                                         unsigned a2, unsigned a3,
                                         unsigned b0, unsigned b1) {
    asm volatile(
        "mma.sync.aligned.m16n8k16.row.col.f32.bf16.bf16.f32 "
        "{%0,%1,%2,%3}, {%4,%5,%6,%7}, {%8,%9}, {%0,%1,%2,%3};"
        : "+f"(d[0]), "+f"(d[1]), "+f"(d[2]), "+f"(d[3])
        : "r"(a0), "r"(a1), "r"(a2), "r"(a3), "r"(b0), "r"(b1));
}

__device__ __forceinline__ unsigned pack_bf2(float a, float b) {
    const __nv_bfloat162 v = __floats2bfloat162_rn(a, b);
    return *reinterpret_cast<const unsigned*>(&v);
}

// word index of the (slot) half of lane entry for GEMM kstep `ks` of tile `tile`
__device__ __forceinline__ int fragB_word(int tile, int ks, int lane, int slot) {
    return ((tile * 8 + ks) * 32 + lane) * 2 + slot;
}

// scatter one bf162 pair (k2-pair index p2 in [0,64)) into A-fragment layout
__device__ __forceinline__ void frag_store(unsigned* fragA, int row, int p2,
                                           unsigned v) {
    const int ks   = p2 >> 3;
    const int tg   = p2 & 3;
    const int hi   = (p2 >> 2) & 1;
    const int lane = ((row & 7) << 2) | tg;
    const int slot = (hi << 1) | (row >> 3);
    fragA[(ks * 32 + lane) * 4 + slot] = v;
}

// ---- the single kernel --------------------------------------------------------
__global__ void __launch_bounds__(TPB, 3)
main_kernel(const float* __restrict__ x,  const float* __restrict__ xv,
            const float* __restrict__ p,  const float* __restrict__ pv,
            float* __restrict__ out) {
    extern __shared__ __align__(16) unsigned smem[];
    unsigned* fragB_w = smem;                       // fragment-layout B
    unsigned* fragA_w = smem + OFF_FRAGA;           // fragment-layout A
    float*    base_s  = reinterpret_cast<float*>(smem + OFF_BASE);
    float*    out_s   = reinterpret_cast<float*>(smem + OFF_OUT);

    const int t    = threadIdx.x;
    const int n0   = blockIdx.x * 16;
    const int lane = t & 31;
    const int w    = t >> 5;

    // ===== phase 0: front-load the x/xv reads ================================
    const int row = t >> 4;              // 0..15
    const int kq  = t & 15;              // 4-k chunk
    const float4 xx = __ldg(reinterpret_cast<const float4*>(
                          x  + (n0 + row) * K_ + kq * 4));
    const float4 vv = __ldg(reinterpret_cast<const float4*>(
                          xv + (n0 + row) * K_ + kq * 4));
    const float v0 = __ldg(pv);

    // ===== own uniformity check + own fragB build (p, pv from L2) ============
    int ok = 1;
    #pragma unroll
    for (int i = 0; i < 12; ++i) {
        const int idx = t * 48 + i * 4;            // float index into p / pv
        if (idx < PVN) {
            const float4 q = __ldg(reinterpret_cast<const float4*>(pv + idx));
            ok &= (q.x == v0) & (q.y == v0) & (q.z == v0) & (q.w == v0);

            const float4 P = __ldg(reinterpret_cast<const float4*>(p + idx));
            const int cm   = idx >> 6;
            const int k    = idx & 63;
            const int tile = cm >> 3;
            const int g2   = cm & 7;
            const float pe[4] = {P.x, P.y, P.z, P.w};
            #pragma unroll
            for (int ii = 0; ii < 2; ++ii) {
                const int kk2  = k + 2 * ii;       // pair start, 0..62
                const int ks   = kk2 >> 4;         // 0..3
                const int lo   = kk2 & 15;
                const int tg2  = (lo & 7) >> 1;
                const int slot = (lo >= 8);
                const int bw   = fragB_word(tile, ks, g2 * 4 + tg2, slot);
                const float a0 = pe[2 * ii], a1 = pe[2 * ii + 1];
                fragB_w[bw]               = pack_bf2(a0 * a0, a1 * a1); // p^2, ks 0..3
                fragB_w[bw + P_KS_OFFSET] = pack_bf2(a0, a1);           // p,   ks 4..7
            }
        } else if (idx < 24 * 8 * 64) {            // zero-pad cm 190,191
            const int cm   = idx >> 6;
            const int k    = idx & 63;
            const int tile = cm >> 3;
            const int g2   = cm & 7;
            #pragma unroll
            for (int ii = 0; ii < 2; ++ii) {
                const int kk2  = k + 2 * ii;
                const int ks   = kk2 >> 4;
                const int lo   = kk2 & 15;
                const int tg2  = (lo & 7) >> 1;
                const int slot = (lo >= 8);
                const int bw   = fragB_word(tile, ks, g2 * 4 + tg2, slot);
                fragB_w[bw]               = 0u;
                fragB_w[bw + P_KS_OFFSET] = 0u;
            }
        }
    }

    // ===== precompute r/a -> fragA, base ====================================
    const float xs[4] = {xx.x, xx.y, xx.z, xx.w};
    const float vs[4] = {vv.x, vv.y, vv.z, vv.w};
    float rr[4], aa[4], prod = 1.0f, sxr = 0.0f;
    #pragma unroll
    for (int e = 0; e < 4; ++e) {
        const float s = vs[e] + v0;
        const float r = __fdividef(1.0f, s);
        prod *= s;
        sxr   = fmaf(xs[e] * xs[e], r, sxr);
        rr[e] = r;
        aa[e] = -2.0f * xs[e] * r;
    }
    frag_store(fragA_w, row, 2 * kq,      pack_bf2(rr[0], rr[1]));
    frag_store(fragA_w, row, 2 * kq + 1,  pack_bf2(rr[2], rr[3]));
    frag_store(fragA_w, row, 32 + 2 * kq, pack_bf2(aa[0], aa[1]));
    frag_store(fragA_w, row, 33 + 2 * kq, pack_bf2(aa[2], aa[3]));

    float tv = sxr + __logf(prod);   // s in (v0, v0+1): no overflow
    tv += __shfl_xor_sync(0xffffffffu, tv, 1);
    tv += __shfl_xor_sync(0xffffffffu, tv, 2);
    tv += __shfl_xor_sync(0xffffffffu, tv, 4);
    tv += __shfl_xor_sync(0xffffffffu, tv, 8);
    if (kq == 0) base_s[row] = tv;

    // one barrier covers fragB, fragA, base; block-wide AND of the check
    const int flag = __syncthreads_and(ok);

    if (flag) {
        // ===== GEMM: one m16 tile; 8 warps x 3 n8-tiles; B from smem =========
        const int g  = lane >> 2;
        const int tg = lane & 3;

        float acc[3][4];
        #pragma unroll
        for (int j = 0; j < 3; ++j)
            #pragma unroll
            for (int q = 0; q < 4; ++q) acc[j][q] = 0.0f;

        const uint2* fragB2 = reinterpret_cast<const uint2*>(fragB_w);
        #pragma unroll
        for (int ks = 0; ks < 8; ++ks) {
            const uint4 A = *reinterpret_cast<const uint4*>(
                &fragA_w[(ks * 32 + lane) * 4]);
            #pragma unroll
            for (int j = 0; j < 3; ++j) {
                const uint2 b = fragB2[((w * 3 + j) * 8 + ks) * 32 + lane];
                mma16816(acc[j], A.x, A.y, A.z, A.w, b.x, b.y);
            }
        }

        // ===== epilogue: stage in smem, then contiguous float4 stores ========
        const float bs0 = base_s[g];
        const float bs1 = base_s[g + 8];
        #pragma unroll
        for (int j = 0; j < 3; ++j) {
            const int cm = (w * 3 + j) * 8 + 2 * tg;
            if (cm < CM_) {
                float2 o0, o1;
                o0.x = -0.0078125f * (acc[j][0] + bs0);
                o0.y = -0.0078125f * (acc[j][1] + bs0);
                o1.x = -0.0078125f * (acc[j][2] + bs1);
                o1.y = -0.0078125f * (acc[j][3] + bs1);
                *reinterpret_cast<float2*>(out_s +  g      * CM_ + cm) = o0;
                *reinterpret_cast<float2*>(out_s + (g + 8) * CM_ + cm) = o1;
            }
        }
        __syncthreads();

        // block output = contiguous span out[n0*190 .. n0*190 + 3040)
        const float4* src = reinterpret_cast<const float4*>(out_s);
        float4* dst = reinterpret_cast<float4*>(out + n0 * CM_);
        #pragma unroll
        for (int i = 0; i < 3; ++i) {
            const int idx = t + i * TPB;
            if (idx < (16 * CM_) / 4) dst[idx] = src[idx];
        }
    } else {
        // ================= GENERAL FALLBACK (non-uniform pv) =================
        for (int idx = t; idx < 16 * CM_; idx += TPB) {
            const int j  = idx / CM_;
            const int cm = idx % CM_;
            const int n  = n0 + j;
            float acc = 0.0f;
            for (int k = 0; k < K_; ++k) {
                const float s = xv[n * K_ + k] + pv[cm * K_ + k];
                const float d = p[cm * K_ + k] - x[n * K_ + k];
                acc += d * d / s + logf(s);
            }
            out[n * CM_ + cm] = -0.5f * acc * (1.0f / (float)K_);
        }
    }
}

// ---- launch -----------------------------------------------------------------
extern "C" void kernel_launch(void* const* d_in, const int* in_sizes, int n_in,
                              void* d_out, int out_size) {
    const float* x  = (const float*)d_in[0];   // [8192,64]
    const float* xv = (const float*)d_in[1];   // [8192,64]
    const float* p  = (const float*)d_in[2];   // [19,10,64]
    const float* pv = (const float*)d_in[3];   // [19,10,64]
    float* out = (float*)d_out;                // [8192,19,10]

    // raise dynamic smem limit (host-side attribute; idempotent, no alloc)
    static int attr_set = 0;
    if (!attr_set) {
        cudaFuncSetAttribute(main_kernel,
                             cudaFuncAttributeMaxDynamicSharedMemorySize,
                             SMEM_BYTES);
        attr_set = 1;
    }

    main_kernel<<<N_ / 16, TPB, SMEM_BYTES>>>(x, xv, p, pv, out);
}